// round 16
// baseline (speedup 1.0000x reference)
#include <cuda_runtime.h>

#define MAXB   16
#define MAXBLK 256
#define TPB    256
#define MAXM   64

__device__ float g_partC[MAXB * MAXBLK];
__device__ float g_partR[MAXB * MAXBLK];
__device__ int   g_partP[MAXB * MAXBLK];
__device__ unsigned int g_done = 0;

#define NEGK (-0.75f * 0.693147180559945f)  /* -(1-alpha) * ln2 */
#define POSK (-0.25f * 0.693147180559945f)  /* -alpha * ln2     */

template<int KT>
__global__ __launch_bounds__(TPB, 6) void focal_main(
    const float* __restrict__ cls,   // [B, A, K]
    const float* __restrict__ reg,   // [B, A, 4]
    const float* __restrict__ anc,   // [1, A, 4]
    const float* __restrict__ ann,   // [B, M, 5]
    int A, int Kr, int M, int nAssign, int nStream, int nBlkTotal,
    float* __restrict__ out)
{
    const int K  = (KT > 0) ? KT : Kr;
    const int K4 = K >> 2;
    const int b   = blockIdx.y;
    const int B   = gridDim.y;
    const int tid = threadIdx.x;

    __shared__ float4 s_box[MAXM];           // x1,y1,x2,y2 (sentinel if padded)
    __shared__ float2 s_meta[MAXM];          // area, label
    __shared__ float  s_redC[TPB], s_redR[TPB];
    __shared__ int    s_redP[TPB];
    __shared__ int    s_isLast;
    __shared__ double shC[MAXB], shR[MAXB];

    float accC = 0.f, accR = 0.f;
    int   accP = 0;

    if (blockIdx.x < nAssign) {
        // ================= ASSIGN role: IoU argmax + corrections =================
        if (tid < M && tid < MAXM) {
            const float* g = ann + ((size_t)b * M + tid) * 5;
            float x1 = g[0], y1 = g[1], x2 = g[2], y2 = g[3], lab = g[4];
            if (lab == -1.0f) {                  // padded GT -> zero-overlap sentinel
                x1 = 3.0e37f; x2 = -3.0e37f; y1 = 0.f; y2 = 0.f;
            }
            s_box[tid]  = make_float4(x1, y1, x2, y2);
            s_meta[tid] = make_float2((lab == -1.0f) ? 0.f : (x2 - x1) * (y2 - y1), lab);
        }
        __syncthreads();

        const int mlim = (M < MAXM) ? M : MAXM;
        const int nTiles = (A + TPB - 1) / TPB;

        for (int tile = blockIdx.x; tile < nTiles; tile += nAssign) {
            const int a = tile * TPB + tid;
            if (a < A) {
                float4 av = __ldg(((const float4*)anc) + a);
                float aarea = (av.z - av.x) * (av.w - av.y);

                // best IoU as (inter, ua) pair; strict > keeps first-argmax ties
                float bi = 0.f, bu = 1.f;
                int   bm = -1;
                #pragma unroll 4
                for (int m = 0; m < mlim; m++) {
                    float4 gb = s_box[m];
                    float2 gm = s_meta[m];
                    float iw = fminf(av.z, gb.z) - fmaxf(av.x, gb.x);
                    float ih = fminf(av.w, gb.w) - fmaxf(av.y, gb.y);
                    float inter = fmaxf(iw, 0.f) * fmaxf(ih, 0.f);
                    float ua = fmaxf(aarea + gm.x - inter, 1e-8f);
                    if (inter * bu > bi * ua) { bi = inter; bu = ua; bm = m; }
                }

                bool pos = (bm >= 0) && (bi >= 0.5f * bu);
                bool neg = (bi < 0.4f * bu);

                if (pos) {
                    accP++;
                    float4 gb = s_box[bm];
                    float aw = av.z - av.x;
                    float ah = av.w - av.y;
                    float gwr = gb.z - gb.x, ghr = gb.w - gb.y;
                    float acx = av.x + 0.5f * aw, acy = av.y + 0.5f * ah;
                    float gcx = gb.x + 0.5f * gwr, gcy = gb.y + 0.5f * ghr;
                    float gw = fmaxf(gwr, 1.f), gh = fmaxf(ghr, 1.f);
                    float t0 = ((gcx - acx) / aw) / 0.1f;
                    float t1 = ((gcy - acy) / ah) / 0.1f;
                    float t2 = logf(gw / aw) / 0.2f;
                    float t3 = logf(gh / ah) / 0.2f;
                    float4 rv = __ldg(((const float4*)reg) + (size_t)b * A + a);
                    float d0 = fabsf(t0 - rv.x);
                    float d1 = fabsf(t1 - rv.y);
                    float d2 = fabsf(t2 - rv.z);
                    float d3 = fabsf(t3 - rv.w);
                    const float TH = 1.0f / 9.0f;
                    const float CC = 0.5f / 9.0f;
                    accR += (d0 <= TH) ? 4.5f * d0 * d0 : d0 - CC;
                    accR += (d1 <= TH) ? 4.5f * d1 * d1 : d1 - CC;
                    accR += (d2 <= TH) ? 4.5f * d2 * d2 : d2 - CC;
                    accR += (d3 <= TH) ? 4.5f * d3 * d3 : d3 - CC;

                    // one-hot lane correction: stream adds NEGK*c^2*lg2(1-c);
                    // replace with the positive focal term at the label lane.
                    int lab = (int)s_meta[bm].y;
                    float c = __ldg(cls + ((size_t)b * A + a) * K + lab);
                    float u = 1.f - c;
                    accC += POSK * u * u * __log2f(c) - NEGK * c * c * __log2f(u);
                } else if (!neg) {
                    // ignore band [0.4, 0.5): rare. Stream added NEGK*S_a;
                    // cancel it by subtracting NEGK*S_a.
                    const float4* row = (const float4*)(cls + ((size_t)b * A + a) * K);
                    float S = 0.f;
                    for (int kk = 0; kk < K4; kk++) {
                        float4 v = __ldg(row + kk);
                        S += v.x * v.x * __log2f(1.f - v.x);
                        S += v.y * v.y * __log2f(1.f - v.y);
                        S += v.z * v.z * __log2f(1.f - v.z);
                        S += v.w * v.w * __log2f(1.f - v.w);
                    }
                    for (int k = K4 << 2; k < K; k++) {
                        float c = __ldg(cls + ((size_t)b * A + a) * K + k);
                        S += c * c * __log2f(1.f - c);
                    }
                    accC -= NEGK * S;
                }
            }
        }
    } else {
        // ================= STREAM role: unconditional weight-free sum =================
        const int sid = blockIdx.x - nAssign;
        const float4* cb = (const float4*)(cls + (size_t)b * A * K);
        const int total  = A * K4;
        const int stride = nStream * TPB;

        float S = 0.f;
        #pragma unroll 4
        for (int i = sid * TPB + tid; i < total; i += stride) {
            float4 v = __ldcs(cb + i);
            float l0 = __log2f(1.f - v.x);
            float l1 = __log2f(1.f - v.y);
            float l2 = __log2f(1.f - v.z);
            float l3 = __log2f(1.f - v.w);
            S += fmaf(v.x * v.x, l0,
                 fmaf(v.y * v.y, l1,
                 fmaf(v.z * v.z, l2, (v.w * v.w) * l3)));
        }
        // scalar tail if K % 4 != 0 (not hit for K=80)
        if (KT == 0) {
            int kRem = K - (K4 << 2);
            if (kRem) {
                const float* cs = cls + (size_t)b * A * K;
                for (int i = sid * TPB + tid; i < A * kRem; i += stride) {
                    int aL = i / kRem;
                    int k  = (K4 << 2) + (i - aL * kRem);
                    float c = __ldg(cs + (size_t)aL * K + k);
                    S += c * c * __log2f(1.f - c);
                }
            }
        }
        accC = NEGK * S;
    }

    // ---- block reduce & write per-block partials ----
    __syncthreads();
    s_redC[tid] = accC;
    s_redR[tid] = accR;
    s_redP[tid] = accP;
    __syncthreads();
    for (int off = TPB / 2; off > 0; off >>= 1) {
        if (tid < off) {
            s_redC[tid] += s_redC[tid + off];
            s_redR[tid] += s_redR[tid + off];
            s_redP[tid] += s_redP[tid + off];
        }
        __syncthreads();
    }
    if (tid == 0) {
        g_partC[b * MAXBLK + blockIdx.x] = s_redC[0];
        g_partR[b * MAXBLK + blockIdx.x] = s_redR[0];
        g_partP[b * MAXBLK + blockIdx.x] = s_redP[0];
        __threadfence();
        unsigned v = atomicAdd(&g_done, 1u);
        s_isLast = (v == (unsigned)(nBlkTotal - 1));
    }
    __syncthreads();

    // ---- last block: fused finalize (one warp per image) ----
    if (s_isLast) {
        __threadfence();
        const int wrp  = tid >> 5;
        const int lane = tid & 31;
        const int nblk = gridDim.x;
        if (wrp < B) {
            float c = 0.f, r = 0.f; int p = 0;
            for (int i = lane; i < nblk; i += 32) {
                c += g_partC[wrp * MAXBLK + i];
                r += g_partR[wrp * MAXBLK + i];
                p += g_partP[wrp * MAXBLK + i];
            }
            #pragma unroll
            for (int off = 16; off > 0; off >>= 1) {
                c += __shfl_down_sync(0xffffffffu, c, off);
                r += __shfl_down_sync(0xffffffffu, r, off);
                p += __shfl_down_sync(0xffffffffu, p, off);
            }
            bool hv = false;
            for (int m = lane; m < M; m += 32)
                if (__ldg(ann + ((size_t)wrp * M + m) * 5 + 4) != -1.0f) hv = true;
            unsigned hvb = __ballot_sync(0xffffffffu, hv);
            if (lane == 0) {
                double cv = 0.0, rv = 0.0;
                if (hvb != 0u) cv = (double)c / (double)(p > 1 ? p : 1);
                if (p > 0) {
                    int d = p * 4 > 1 ? p * 4 : 1;
                    rv = (double)r / (double)d;
                }
                shC[wrp] = cv;
                shR[wrp] = rv;
            }
        }
        __syncthreads();
        if (tid == 0) {
            double cs = 0.0, rs = 0.0;
            for (int i = 0; i < B; i++) { cs += shC[i]; rs += shR[i]; }
            out[0] = (float)(cs / (double)B);
            out[1] = (float)(rs / (double)B);
            atomicExch(&g_done, 0u);   // reset for graph replay
        }
    }
}

extern "C" void kernel_launch(void* const* d_in, const int* in_sizes, int n_in,
                              void* d_out, int out_size) {
    const float* cls = (const float*)d_in[0];
    const float* reg = (const float*)d_in[1];
    const float* anc = (const float*)d_in[2];
    const float* ann = (const float*)d_in[3];

    int A = in_sizes[2] / 4;                                        // anchors [1,A,4]
    int B = in_sizes[1] / (A * 4);                                  // regressions [B,A,4]
    int K = (int)((long long)in_sizes[0] / ((long long)A * B));     // cls [B,A,K]
    int M = in_sizes[3] / (B * 5);                                  // annotations [B,M,5]

    // one fully-resident wave: 6 blocks/SM * 148 SMs = 888 slots
    int perImg = (148 * 6) / (B > 0 ? B : 1);    // 111 for B=8
    if (perImg < 2) perImg = 2;
    if (perImg > MAXBLK) perImg = MAXBLK;
    int nAssign = perImg / 3;                    // issue-heavy role (~1/3)
    if (nAssign < 1) nAssign = 1;
    int nTilesA = (A + TPB - 1) / TPB;
    if (nAssign > nTilesA) nAssign = nTilesA;
    int nStream = perImg - nAssign;
    if (nStream < 1) nStream = 1;
    int gx = nAssign + nStream;
    dim3 grid(gx, B);

    if (K == 80)
        focal_main<80><<<grid, TPB>>>(cls, reg, anc, ann, A, K, M,
                                      nAssign, nStream, gx * B, (float*)d_out);
    else
        focal_main<0><<<grid, TPB>>>(cls, reg, anc, ann, A, K, M,
                                     nAssign, nStream, gx * B, (float*)d_out);
}

// round 17
// speedup vs baseline: 1.3558x; 1.3558x over previous
#include <cuda_runtime.h>

#define MAXB   16
#define MAXBLK 256
#define TPB    256
#define MAXM   64

__device__ float g_partC[MAXB * MAXBLK];
__device__ float g_partR[MAXB * MAXBLK];
__device__ int   g_partP[MAXB * MAXBLK];
__device__ unsigned int g_done = 0;

#define NEGK (-0.75f * 0.693147180559945f)  /* -(1-alpha) * ln2 */
#define POSK (-0.25f * 0.693147180559945f)  /* -alpha * ln2     */

template<int KT>
__global__ __launch_bounds__(TPB, 6) void focal_main(
    const float* __restrict__ cls,   // [B, A, K]
    const float* __restrict__ reg,   // [B, A, 4]
    const float* __restrict__ anc,   // [1, A, 4]
    const float* __restrict__ ann,   // [B, M, 5]
    int A, int Kr, int M, int nTiles, int nBlkTotal, float* __restrict__ out)
{
    const int K  = (KT > 0) ? KT : Kr;
    const int K4 = K >> 2;
    const int b   = blockIdx.y;
    const int B   = gridDim.y;
    const int tid = threadIdx.x;

    __shared__ float4 s_box[MAXM];           // x1,y1,x2,y2 (sentinel if padded)
    __shared__ float2 s_meta[MAXM];          // area, label
    __shared__ float  s_redC[TPB], s_redR[TPB];
    __shared__ int    s_redP[TPB];
    __shared__ int    s_isLast;
    __shared__ double shC[MAXB], shR[MAXB];

    // ---- load & preprocess GT annotations for this image ----
    if (tid < M && tid < MAXM) {
        const float* g = ann + ((size_t)b * M + tid) * 5;
        float x1 = g[0], y1 = g[1], x2 = g[2], y2 = g[3], lab = g[4];
        if (lab == -1.0f) {                      // padded GT -> zero-overlap sentinel
            x1 = 3.0e37f; x2 = -3.0e37f; y1 = 0.f; y2 = 0.f;
        }
        s_box[tid]  = make_float4(x1, y1, x2, y2);
        s_meta[tid] = make_float2((lab == -1.0f) ? 0.f : (x2 - x1) * (y2 - y1), lab);
    }
    __syncthreads();   // the ONLY barrier before the reduction

    float accC = 0.f, accR = 0.f;
    float S    = 0.f;                          // unconditional streaming sum
    int   accP = 0;
    const int mlim = (M < MAXM) ? M : MAXM;

    for (int tile = blockIdx.x; tile < nTiles; tile += gridDim.x) {
        const int a0 = tile * TPB;
        const int a  = a0 + tid;

        // ---- phase 1: per-anchor IoU argmax -> corrections only (no weights) ----
        if (a < A) {
            float4 av = __ldg(((const float4*)anc) + a);
            float aarea = (av.z - av.x) * (av.w - av.y);

            // best IoU as (inter, ua) pair; strict > keeps first-argmax tie semantics
            float bi = 0.f, bu = 1.f;
            int   bm = -1;
            #pragma unroll 4
            for (int m = 0; m < mlim; m++) {
                float4 gb = s_box[m];
                float2 gm = s_meta[m];
                float iw = fminf(av.z, gb.z) - fmaxf(av.x, gb.x);
                float ih = fminf(av.w, gb.w) - fmaxf(av.y, gb.y);
                float inter = fmaxf(iw, 0.f) * fmaxf(ih, 0.f);
                float ua = fmaxf(aarea + gm.x - inter, 1e-8f);
                if (inter * bu > bi * ua) { bi = inter; bu = ua; bm = m; }
            }

            bool pos = (bm >= 0) && (bi >= 0.5f * bu);
            bool neg = (bi < 0.4f * bu);

            if (pos) {
                accP++;
                float4 gb = s_box[bm];
                float aw = av.z - av.x;
                float ah = av.w - av.y;
                float gwr = gb.z - gb.x, ghr = gb.w - gb.y;
                float acx = av.x + 0.5f * aw, acy = av.y + 0.5f * ah;
                float gcx = gb.x + 0.5f * gwr, gcy = gb.y + 0.5f * ghr;
                float gw = fmaxf(gwr, 1.f), gh = fmaxf(ghr, 1.f);
                float t0 = ((gcx - acx) / aw) / 0.1f;
                float t1 = ((gcy - acy) / ah) / 0.1f;
                float t2 = logf(gw / aw) / 0.2f;
                float t3 = logf(gh / ah) / 0.2f;
                float4 rv = __ldg(((const float4*)reg) + (size_t)b * A + a);
                float d0 = fabsf(t0 - rv.x);
                float d1 = fabsf(t1 - rv.y);
                float d2 = fabsf(t2 - rv.z);
                float d3 = fabsf(t3 - rv.w);
                const float TH = 1.0f / 9.0f;
                const float CC = 0.5f / 9.0f;
                accR += (d0 <= TH) ? 4.5f * d0 * d0 : d0 - CC;
                accR += (d1 <= TH) ? 4.5f * d1 * d1 : d1 - CC;
                accR += (d2 <= TH) ? 4.5f * d2 * d2 : d2 - CC;
                accR += (d3 <= TH) ? 4.5f * d3 * d3 : d3 - CC;

                // one-hot lane correction: stream adds NEGK*c^2*lg2(1-c);
                // replace it with the positive focal term at the label lane.
                int lab = (int)s_meta[bm].y;
                float c = __ldg(cls + ((size_t)b * A + a) * K + lab);
                float u = 1.f - c;
                accC += POSK * u * u * __log2f(c) - NEGK * c * c * __log2f(u);
            } else if (!neg) {
                // ignore band [0.4,0.5): rare. Stream will add NEGK*S_a for this
                // whole row; cancel it here (row is L2-warm or cheap re-read).
                const float4* row = (const float4*)(cls + ((size_t)b * A + a) * K);
                float Sa = 0.f;
                for (int kk = 0; kk < K4; kk++) {
                    float4 v = __ldg(row + kk);
                    float l0 = __log2f(1.f - v.x);
                    float l1 = __log2f(1.f - v.y);
                    float l2 = __log2f(1.f - v.z);
                    float l3 = __log2f(1.f - v.w);
                    Sa += fmaf(v.x * v.x, l0,
                          fmaf(v.y * v.y, l1,
                          fmaf(v.z * v.z, l2, (v.w * v.w) * l3)));
                }
                for (int k = K4 << 2; k < K; k++) {
                    float c = __ldg(cls + ((size_t)b * A + a) * K + k);
                    Sa += c * c * __log2f(1.f - c);
                }
                accC -= NEGK * Sa;
            }
        }

        // ---- phase 2: unconditional coalesced stream (no weights, no barrier) ----
        int nA = A - a0; if (nA > TPB) nA = TPB;
        const float4* cb = (const float4*)(cls + ((size_t)b * A + (size_t)a0) * K);

        if (KT > 0 && nA == TPB) {
            constexpr int ITERS = (KT > 0) ? (KT / 4) : 1;
            #pragma unroll 5
            for (int j = 0; j < ITERS; j++) {
                float4 v = __ldcs(cb + j * TPB + tid);
                float l0 = __log2f(1.f - v.x);
                float l1 = __log2f(1.f - v.y);
                float l2 = __log2f(1.f - v.z);
                float l3 = __log2f(1.f - v.w);
                S += fmaf(v.x * v.x, l0,
                     fmaf(v.y * v.y, l1,
                     fmaf(v.z * v.z, l2, (v.w * v.w) * l3)));
            }
        } else {
            int total = nA * K4;
            for (int i = tid; i < total; i += TPB) {
                float4 v = __ldcs(cb + i);
                float l0 = __log2f(1.f - v.x);
                float l1 = __log2f(1.f - v.y);
                float l2 = __log2f(1.f - v.z);
                float l3 = __log2f(1.f - v.w);
                S += fmaf(v.x * v.x, l0,
                     fmaf(v.y * v.y, l1,
                     fmaf(v.z * v.z, l2, (v.w * v.w) * l3)));
            }
            int kRem = K - (K4 << 2);
            if (kRem) {
                for (int i = tid; i < nA * kRem; i += TPB) {
                    int aL = i / kRem;
                    int k  = (K4 << 2) + (i - aL * kRem);
                    float c = __ldg(cls + ((size_t)b * A + a0 + aL) * K + k);
                    S += c * c * __log2f(1.f - c);
                }
            }
        }
        // no __syncthreads(): phases share nothing; warps free-run
    }
    accC = fmaf(NEGK, S, accC);   // fold the streaming sum once

    // ---- block reduce & write per-block partials ----
    __syncthreads();
    s_redC[tid] = accC;
    s_redR[tid] = accR;
    s_redP[tid] = accP;
    __syncthreads();
    for (int off = TPB / 2; off > 0; off >>= 1) {
        if (tid < off) {
            s_redC[tid] += s_redC[tid + off];
            s_redR[tid] += s_redR[tid + off];
            s_redP[tid] += s_redP[tid + off];
        }
        __syncthreads();
    }
    if (tid == 0) {
        g_partC[b * MAXBLK + blockIdx.x] = s_redC[0];
        g_partR[b * MAXBLK + blockIdx.x] = s_redR[0];
        g_partP[b * MAXBLK + blockIdx.x] = s_redP[0];
        __threadfence();
        unsigned v = atomicAdd(&g_done, 1u);
        s_isLast = (v == (unsigned)(nBlkTotal - 1));
    }
    __syncthreads();

    // ---- last block: fused finalize (one warp per image) ----
    if (s_isLast) {
        __threadfence();
        const int wrp  = tid >> 5;
        const int lane = tid & 31;
        const int nblk = gridDim.x;
        if (wrp < B) {
            float c = 0.f, r = 0.f; int p = 0;
            for (int i = lane; i < nblk; i += 32) {
                c += g_partC[wrp * MAXBLK + i];
                r += g_partR[wrp * MAXBLK + i];
                p += g_partP[wrp * MAXBLK + i];
            }
            #pragma unroll
            for (int off = 16; off > 0; off >>= 1) {
                c += __shfl_down_sync(0xffffffffu, c, off);
                r += __shfl_down_sync(0xffffffffu, r, off);
                p += __shfl_down_sync(0xffffffffu, p, off);
            }
            bool hv = false;
            for (int m = lane; m < M; m += 32)
                if (__ldg(ann + ((size_t)wrp * M + m) * 5 + 4) != -1.0f) hv = true;
            unsigned hvb = __ballot_sync(0xffffffffu, hv);
            if (lane == 0) {
                double cv = 0.0, rv = 0.0;
                if (hvb != 0u) cv = (double)c / (double)(p > 1 ? p : 1);
                if (p > 0) {
                    int d = p * 4 > 1 ? p * 4 : 1;
                    rv = (double)r / (double)d;
                }
                shC[wrp] = cv;
                shR[wrp] = rv;
            }
        }
        __syncthreads();
        if (tid == 0) {
            double cs = 0.0, rs = 0.0;
            for (int i = 0; i < B; i++) { cs += shC[i]; rs += shR[i]; }
            out[0] = (float)(cs / (double)B);
            out[1] = (float)(rs / (double)B);
            atomicExch(&g_done, 0u);   // reset for graph replay
        }
    }
}

extern "C" void kernel_launch(void* const* d_in, const int* in_sizes, int n_in,
                              void* d_out, int out_size) {
    const float* cls = (const float*)d_in[0];
    const float* reg = (const float*)d_in[1];
    const float* anc = (const float*)d_in[2];
    const float* ann = (const float*)d_in[3];

    int A = in_sizes[2] / 4;                                        // anchors [1,A,4]
    int B = in_sizes[1] / (A * 4);                                  // regressions [B,A,4]
    int K = (int)((long long)in_sizes[0] / ((long long)A * B));     // cls [B,A,K]
    int M = in_sizes[3] / (B * 5);                                  // annotations [B,M,5]

    int nTiles = (A + TPB - 1) / TPB;
    int gx0 = (148 * 6) / (B > 0 ? B : 1);      // round-6 grid: 6 blocks/SM target
    if (gx0 < 1) gx0 = 1;
    int tpb = (nTiles + gx0 - 1) / gx0;         // balanced tiles per block
    int gx  = (nTiles + tpb - 1) / tpb;
    if (gx > MAXBLK) gx = MAXBLK;
    if (gx < 1) gx = 1;
    dim3 grid(gx, B);

    if (K == 80)
        focal_main<80><<<grid, TPB>>>(cls, reg, anc, ann, A, K, M, nTiles, gx * B, (float*)d_out);
    else
        focal_main<0><<<grid, TPB>>>(cls, reg, anc, ann, A, K, M, nTiles, gx * B, (float*)d_out);
}